// round 11
// baseline (speedup 1.0000x reference)
#include <cuda_runtime.h>
#include <cuda_bf16.h>
#include <math.h>
#include <mma.h>
#include <stdint.h>

using namespace nvcuda;

// ---------------- problem constants ----------------
#define NN   8192
#define NE   32768
#define NB   64
#define DF   64
#define NFI  32
#define EFI  16
#define NOUT 12
#define TMP  3
#define TS2S 12

#define KCH    32                 // k values per chunk
#define NCHUNK (DF / KCH)         // 2 chunks
#define TCC    (KCH * DF)         // 2048 columns per Tc chunk

// ---------------- device scratch ----------------
__device__ __align__(16) float g_ed[NE * DF];                   // 8 MB
__device__ __align__(16) __nv_bfloat16 g_W2bh[DF * 4096];       // W2 perm bf16-hi
__device__ __align__(16) __nv_bfloat16 g_W2bl[DF * 4096];       // W2 perm bf16-lo
__device__ __align__(16) __nv_bfloat16 g_Whbh[DF * 256];        // [W_hh|B2] bf16-hi
__device__ __align__(16) __nv_bfloat16 g_Whbl[DF * 256];        // [W_hh|B2] bf16-lo
__device__ __align__(16) float g_Tc[(size_t)NN * TCC];          // 67 MB (L2-resident)
__device__ __align__(16) float g_ghb[NN * 256];                 // 8 MB
__device__ __align__(16) float g_h[NN * DF];                    // 2 MB
__device__ __align__(16) __nv_bfloat16 g_hbh[NN * DF];          // 1 MB
__device__ __align__(16) __nv_bfloat16 g_hbl[NN * DF];          // 1 MB
__device__ __align__(16) float g_msg[(size_t)NE * DF];          // per-edge message, 8 MB
__device__ __align__(16) float g_agg[NN * DF];                  // 2 MB
__device__ __align__(16) float g_gi[NN * 3 * DF];               // 6 MB
__device__ int g_segoff[NB + 1];
__device__ int g_scnt[NN], g_scur[NN], g_ssorted[NE], g_soff[NN + 1];   // src sort
__device__ int g_tcnt[NN], g_tcur[NN], g_tsorted[NE], g_toff[NN + 1];   // tgt sort

__device__ __forceinline__ float sigmoidf_(float x) { return 1.0f / (1.0f + expf(-x)); }

__device__ __forceinline__ void split_bf16(float x, __nv_bfloat16& hi, __nv_bfloat16& lo) {
    hi = __float2bfloat16(x);
    lo = __float2bfloat16(x - __bfloat162float(hi));
}

// ---------------- prep: pack + bf16-split W2 (k-major) and Whb = [W_hh | B2] ----------------
__global__ void prep_kernel(const float* __restrict__ W_ee2,
                            const float* __restrict__ b_ee2,
                            const float* __restrict__ W_hh) {
    int idx = blockIdx.x * blockDim.x + threadIdx.x;
    if (idx < DF * 4096) {
        int j = idx >> 12;
        int c = idx & 4095;
        int k = c >> 6, i = c & 63;
        float v = W_ee2[k * 4096 + i * 64 + j];
        __nv_bfloat16 hi, lo; split_bf16(v, hi, lo);
        g_W2bh[idx] = hi; g_W2bl[idx] = lo;
    } else if (idx < DF * 4096 + DF * 256) {
        int idx2 = idx - DF * 4096;
        int j = idx2 >> 8;
        int c = idx2 & 255;
        float v = (c < 192) ? W_hh[j * 192 + c] : b_ee2[(c - 192) * 64 + j];
        __nv_bfloat16 hi, lo; split_bf16(v, hi, lo);
        g_Whbh[idx2] = hi; g_Whbl[idx2] = lo;
    }
}

// ---------------- edge encoder layer 1 ----------------
__global__ void edge_enc_kernel(const float* __restrict__ ef,
                                const float* __restrict__ W1,
                                const float* __restrict__ b1) {
    __shared__ float w1s[EFI * DF];
    __shared__ float b1s[DF];
    __shared__ float efs[4][EFI];
    int tid = threadIdx.x;
    int e0 = blockIdx.x * 4;
    for (int it = tid; it < EFI * DF; it += 256) w1s[it] = W1[it];
    if (tid < DF) b1s[tid] = b1[tid];
    if (tid < 4 * EFI) efs[tid / EFI][tid % EFI] = ef[(e0 + tid / EFI) * EFI + (tid % EFI)];
    __syncthreads();
    int le = tid / DF;
    int d  = tid % DF;
    float acc = b1s[d];
#pragma unroll
    for (int f = 0; f < EFI; f++) acc += efs[le][f] * w1s[f * DF + d];
    g_ed[(e0 + le) * DF + d] = fmaxf(acc, 0.0f);
}

// ---------------- input projection (+ bf16 hi/lo split) ----------------
__global__ void input_proj_kernel(const float* __restrict__ nf,
                                  const float* __restrict__ W,
                                  const float* __restrict__ b) {
    __shared__ float ws[NFI * DF];
    __shared__ float bs[DF];
    __shared__ float nfs[4][NFI];
    int tid = threadIdx.x;
    int n0 = blockIdx.x * 4;
    for (int it = tid; it < NFI * DF; it += 256) ws[it] = W[it];
    if (tid < DF) bs[tid] = b[tid];
    if (tid < 4 * NFI) nfs[tid / NFI][tid % NFI] = nf[(n0 + tid / NFI) * NFI + (tid % NFI)];
    __syncthreads();
    int ln = tid / DF;
    int d  = tid % DF;
    float acc = bs[d];
#pragma unroll
    for (int f = 0; f < NFI; f++) acc += nfs[ln][f] * ws[f * DF + d];
    int o = (n0 + ln) * DF + d;
    g_h[o] = acc;
    __nv_bfloat16 hi, lo; split_bf16(acc, hi, lo);
    g_hbh[o] = hi; g_hbl[o] = lo;
}

// ---------------- segment offsets (batch sorted) ----------------
__global__ void segoff_kernel(const int* __restrict__ batch) {
    int g = threadIdx.x;
    if (g > NB) return;
    if (g == NB) { g_segoff[NB] = NN; return; }
    int lo = 0, hi = NN;
    while (lo < hi) { int mid = (lo + hi) >> 1; if (batch[mid] < g) lo = mid + 1; else hi = mid; }
    g_segoff[g] = lo;
}

// ---------------- generic counting sort: count / scan / scatter ----------------
__global__ void count_kernel(const int* __restrict__ key, int* __restrict__ cnt) {
    int e = blockIdx.x * blockDim.x + threadIdx.x;
    if (e < NE) atomicAdd(&cnt[key[e]], 1);
}

__global__ void scan_kernel(const int* __restrict__ cnt, int* __restrict__ cur,
                            int* __restrict__ off) {
    __shared__ int part[1024];
    int tid = threadIdx.x;
    int loc[8]; int s = 0;
#pragma unroll
    for (int i = 0; i < 8; i++) { loc[i] = s; s += cnt[tid * 8 + i]; }
    part[tid] = s;
    __syncthreads();
    for (int o = 1; o < 1024; o <<= 1) {
        int t = (tid >= o) ? part[tid - o] : 0;
        __syncthreads();
        part[tid] += t;
        __syncthreads();
    }
    int excl = tid ? part[tid - 1] : 0;
#pragma unroll
    for (int i = 0; i < 8; i++) { cur[tid * 8 + i] = excl + loc[i]; off[tid * 8 + i] = excl + loc[i]; }
    if (tid == 1023) off[NN] = NE;
}

__global__ void scatter_kernel(const int* __restrict__ key, int* __restrict__ cur,
                               int* __restrict__ sorted) {
    int e = blockIdx.x * blockDim.x + threadIdx.x;
    if (e >= NE) return;
    int p = atomicAdd(&cur[key[e]], 1);
    sorted[p] = e;
}

// ---------------- bf16x3 tensor-core GEMM (R9-proven): C = (Ah+Al) @ (Bh+Bl) ----------------
__global__ void gemm_bf16x3_kernel(const __nv_bfloat16* __restrict__ Abh,
                                   const __nv_bfloat16* __restrict__ Abl,
                                   const __nv_bfloat16* __restrict__ Bbh,
                                   const __nv_bfloat16* __restrict__ Bbl,
                                   float* __restrict__ C, int ldb, int ldc) {
    __shared__ __nv_bfloat16 Ah[64][72], Al[64][72], Bh[64][72], Bl[64][72];
    int tid = threadIdx.x;
    int m0 = blockIdx.y * 64;
    int n0 = blockIdx.x * 64;
#pragma unroll
    for (int it = 0; it < 4; it++) {
        int idx = tid + it * 128;
        int row = idx >> 3;
        int c8  = (idx & 7) << 3;
        *(uint4*)&Ah[row][c8] = *(const uint4*)&Abh[(size_t)(m0 + row) * 64 + c8];
        *(uint4*)&Al[row][c8] = *(const uint4*)&Abl[(size_t)(m0 + row) * 64 + c8];
        *(uint4*)&Bh[row][c8] = *(const uint4*)&Bbh[(size_t)row * ldb + n0 + c8];
        *(uint4*)&Bl[row][c8] = *(const uint4*)&Bbl[(size_t)row * ldb + n0 + c8];
    }
    __syncthreads();
    int warp = tid >> 5;
    int wm = warp >> 1;
    int wn = warp & 1;
    wmma::fragment<wmma::accumulator, 16, 16, 16, float> acc[2][2];
#pragma unroll
    for (int i = 0; i < 2; i++)
#pragma unroll
        for (int j = 0; j < 2; j++) wmma::fill_fragment(acc[i][j], 0.0f);
#pragma unroll
    for (int ks = 0; ks < 4; ks++) {
        wmma::fragment<wmma::matrix_a, 16, 16, 16, __nv_bfloat16, wmma::row_major> ah[2], al[2];
        wmma::fragment<wmma::matrix_b, 16, 16, 16, __nv_bfloat16, wmma::row_major> bh[2], bl[2];
#pragma unroll
        for (int i = 0; i < 2; i++) {
            wmma::load_matrix_sync(ah[i], &Ah[wm * 32 + i * 16][ks * 16], 72);
            wmma::load_matrix_sync(al[i], &Al[wm * 32 + i * 16][ks * 16], 72);
        }
#pragma unroll
        for (int j = 0; j < 2; j++) {
            wmma::load_matrix_sync(bh[j], &Bh[ks * 16][wn * 32 + j * 16], 72);
            wmma::load_matrix_sync(bl[j], &Bl[ks * 16][wn * 32 + j * 16], 72);
        }
#pragma unroll
        for (int i = 0; i < 2; i++)
#pragma unroll
            for (int j = 0; j < 2; j++) {
                wmma::mma_sync(acc[i][j], al[i], bh[j], acc[i][j]);
                wmma::mma_sync(acc[i][j], ah[i], bl[j], acc[i][j]);
                wmma::mma_sync(acc[i][j], ah[i], bh[j], acc[i][j]);
            }
    }
#pragma unroll
    for (int i = 0; i < 2; i++)
#pragma unroll
        for (int j = 0; j < 2; j++)
            wmma::store_matrix_sync(
                &C[(size_t)(m0 + wm * 32 + i * 16) * ldc + n0 + wn * 32 + j * 16],
                acc[i][j], ldc, wmma::mem_row_major);
}

// ---------------- legacy tf32x3 GEMM (gi = agg @ W_ih only) ----------------
__global__ void gemm_tf32x3_kernel(const float* __restrict__ A,
                                   const float* __restrict__ Bm,
                                   float* __restrict__ C,
                                   int ldb, int ldc) {
    __shared__ float As[64][68];
    __shared__ float Bs[64][68];
    int tid = threadIdx.x;
    int m0 = blockIdx.y * 64;
    int n0 = blockIdx.x * 64;
#pragma unroll
    for (int it = 0; it < 8; it++) {
        int idx = tid + it * 128;
        int row = idx >> 4;
        int c4  = (idx & 15) << 2;
        float4 va = *(const float4*)&A[(size_t)(m0 + row) * 64 + c4];
        As[row][c4 + 0] = va.x; As[row][c4 + 1] = va.y;
        As[row][c4 + 2] = va.z; As[row][c4 + 3] = va.w;
        float4 vb = *(const float4*)&Bm[(size_t)row * ldb + n0 + c4];
        Bs[row][c4 + 0] = vb.x; Bs[row][c4 + 1] = vb.y;
        Bs[row][c4 + 2] = vb.z; Bs[row][c4 + 3] = vb.w;
    }
    __syncthreads();
    int warp = tid >> 5;
    int wm = warp >> 1;
    int wn = warp & 1;
    wmma::fragment<wmma::accumulator, 16, 16, 8, float> acc[2][2];
#pragma unroll
    for (int i = 0; i < 2; i++)
#pragma unroll
        for (int j = 0; j < 2; j++) wmma::fill_fragment(acc[i][j], 0.0f);
#pragma unroll
    for (int ks = 0; ks < 8; ks++) {
        wmma::fragment<wmma::matrix_a, 16, 16, 8, wmma::precision::tf32, wmma::row_major> ah[2], al[2];
        wmma::fragment<wmma::matrix_b, 16, 16, 8, wmma::precision::tf32, wmma::row_major> bh[2], bl[2];
#pragma unroll
        for (int i = 0; i < 2; i++) {
            wmma::load_matrix_sync(ah[i], &As[wm * 32 + i * 16][ks * 8], 68);
#pragma unroll
            for (int t = 0; t < ah[i].num_elements; t++) {
                float x  = ah[i].x[t];
                float hi = wmma::__float_to_tf32(x);
                al[i].x[t] = wmma::__float_to_tf32(x - hi);
                ah[i].x[t] = hi;
            }
        }
#pragma unroll
        for (int j = 0; j < 2; j++) {
            wmma::load_matrix_sync(bh[j], &Bs[ks * 8][wn * 32 + j * 16], 68);
#pragma unroll
            for (int t = 0; t < bh[j].num_elements; t++) {
                float x  = bh[j].x[t];
                float hi = wmma::__float_to_tf32(x);
                bl[j].x[t] = wmma::__float_to_tf32(x - hi);
                bh[j].x[t] = hi;
            }
        }
#pragma unroll
        for (int i = 0; i < 2; i++)
#pragma unroll
            for (int j = 0; j < 2; j++) {
                wmma::mma_sync(acc[i][j], al[i], bh[j], acc[i][j]);
                wmma::mma_sync(acc[i][j], ah[i], bl[j], acc[i][j]);
                wmma::mma_sync(acc[i][j], ah[i], bh[j], acc[i][j]);
            }
    }
#pragma unroll
    for (int i = 0; i < 2; i++)
#pragma unroll
        for (int j = 0; j < 2; j++)
            wmma::store_matrix_sync(
                &C[(size_t)(m0 + wm * 32 + i * 16) * ldc + n0 + wn * 32 + j * 16],
                acc[i][j], ldc, wmma::mem_row_major);
}

// ---------------- per-src message chunk: msg[e] += ed[e,kc] . Tc[src] (no atomics) ----
// 256 threads = 4 srcs x 64 lanes. Lane i caches its Trow slice in 32 regs, loops edges.
__global__ void node_msg_chunk_kernel(int kc, int last) {
    int tid = threadIdx.x;
    int ls  = tid >> 6;                // local src 0..3
    int i   = tid & 63;
    int s   = blockIdx.x * 4 + ls;
    int beg = g_soff[s], end = g_soff[s + 1];
    if (beg == end) return;
    const float* Trow = &g_Tc[(size_t)s * TCC];
    float tr[KCH];
#pragma unroll
    for (int kk = 0; kk < KCH; kk++) tr[kk] = Trow[kk * DF + i];
    float bias = last ? g_ghb[s * 256 + 192 + i] : 0.0f;
    for (int j = beg; j < end; j++) {
        int e = g_ssorted[j];
        const float4* ed4 = (const float4*)&g_ed[e * DF + kc * KCH];
        float acc = bias;
#pragma unroll
        for (int q = 0; q < KCH / 4; q++) {
            float4 v = ed4[q];          // broadcast across lanes
            acc += v.x * tr[q * 4 + 0] + v.y * tr[q * 4 + 1]
                 + v.z * tr[q * 4 + 2] + v.w * tr[q * 4 + 3];
        }
        float* m = &g_msg[(size_t)e * DF + i];
        if (kc == 0) *m = acc; else *m += acc;
    }
}

// ---------------- tgt-sorted segmented sum: agg[t] = sum msg[e] (no atomics) ----------------
__global__ void reduce_agg_kernel() {
    int tid = threadIdx.x;
    int lt  = tid >> 6;
    int i   = tid & 63;
    int t   = blockIdx.x * 4 + lt;
    int beg = g_toff[t], end = g_toff[t + 1];
    float acc = 0.0f;
    for (int j = beg; j < end; j++)
        acc += g_msg[(size_t)g_tsorted[j] * DF + i];
    g_agg[t * DF + i] = acc;
}

// ---------------- GRU update; writes h + bf16 hi/lo ----------------
__global__ void gru_kernel(const float* __restrict__ b_ih,
                           const float* __restrict__ b_hh) {
    int idx = blockIdx.x * blockDim.x + threadIdx.x;
    if (idx >= NN * DF) return;
    int n = idx / DF;
    int d = idx % DF;
    const float* ghrow = &g_ghb[n * 256];
    float gh_r = ghrow[d]       + b_hh[d];
    float gh_z = ghrow[64 + d]  + b_hh[64 + d];
    float gh_n = ghrow[128 + d] + b_hh[128 + d];
    const float* gi = &g_gi[n * 192];
    float gi_r = gi[d]       + b_ih[d];
    float gi_z = gi[64 + d]  + b_ih[64 + d];
    float gi_n = gi[128 + d] + b_ih[128 + d];
    float r = sigmoidf_(gi_r + gh_r);
    float z = sigmoidf_(gi_z + gh_z);
    float nn = tanhf(gi_n + r * gh_n);
    float h = g_h[idx];
    float v = (1.0f - z) * nn + z * h;
    g_h[idx] = v;
    __nv_bfloat16 hi, lo; split_bf16(v, hi, lo);
    g_hbh[idx] = hi; g_hbl[idx] = lo;
}

// ---------------- fused Set2Set + output head ----------------
#define MAXSEG 2048
__global__ void set2set_kernel(const float* __restrict__ Wl_ih,
                               const float* __restrict__ Wl_hh,
                               const float* __restrict__ bl_ih,
                               const float* __restrict__ bl_hh,
                               const float* __restrict__ W_out,
                               const float* __restrict__ b_out,
                               float* __restrict__ out) {
    __shared__ float q[DF], hs[DF], cs[DF], qstar[2 * DF], gates[4 * DF];
    __shared__ float evals[MAXSEG];
    __shared__ float redmax[8], redsum[8];
    int b   = blockIdx.x;
    int tid = threadIdx.x;
    int lane = tid & 31, w = tid >> 5;
    int start = g_segoff[b], end = g_segoff[b + 1];
    int cnt = end - start;
    if (tid < DF) { hs[tid] = 0.0f; cs[tid] = 0.0f; }
    if (tid < 2 * DF) qstar[tid] = 0.0f;
    __syncthreads();

    for (int s = 0; s < TS2S; s++) {
        float acc = bl_ih[tid] + bl_hh[tid];
#pragma unroll 4
        for (int j = 0; j < 2 * DF; j++) acc += qstar[j] * Wl_ih[j * 256 + tid];
#pragma unroll 4
        for (int j = 0; j < DF; j++)     acc += hs[j] * Wl_hh[j * 256 + tid];
        gates[tid] = acc;
        __syncthreads();
        if (tid < DF) {
            float i_ = gates[tid], f_ = gates[64 + tid], g_ = gates[128 + tid], o_ = gates[192 + tid];
            float cc = sigmoidf_(f_) * cs[tid] + sigmoidf_(i_) * tanhf(g_);
            cs[tid] = cc;
            float hh = sigmoidf_(o_) * tanhf(cc);
            hs[tid] = hh;
            q[tid] = hh;
        }
        __syncthreads();
        if (s == TS2S - 1) break;

        if (cnt > 0) {
            for (int idx = w; idx < cnt; idx += 8) {
                const float* xr = &g_h[(size_t)(start + idx) * DF];
                float p = xr[lane] * q[lane] + xr[lane + 32] * q[lane + 32];
#pragma unroll
                for (int o = 16; o; o >>= 1) p += __shfl_xor_sync(0xffffffffu, p, o);
                if (lane == 0) evals[idx] = p;
            }
            __syncthreads();
            float m = -INFINITY;
            for (int idx = tid; idx < cnt; idx += 256) m = fmaxf(m, evals[idx]);
#pragma unroll
            for (int o = 16; o; o >>= 1) m = fmaxf(m, __shfl_xor_sync(0xffffffffu, m, o));
            if (lane == 0) redmax[w] = m;
            __syncthreads();
            float emax = redmax[0];
#pragma unroll
            for (int k = 1; k < 8; k++) emax = fmaxf(emax, redmax[k]);
            float dsum = 0.0f;
            for (int idx = tid; idx < cnt; idx += 256) {
                float ex = expf(evals[idx] - emax);
                evals[idx] = ex;
                dsum += ex;
            }
#pragma unroll
            for (int o = 16; o; o >>= 1) dsum += __shfl_xor_sync(0xffffffffu, dsum, o);
            if (lane == 0) redsum[w] = dsum;
            __syncthreads();
            float denom = 0.0f;
#pragma unroll
            for (int k = 0; k < 8; k++) denom += redsum[k];
            if (tid < DF) {
                float r = 0.0f;
                for (int idx = 0; idx < cnt; idx++)
                    r += evals[idx] * g_h[(size_t)(start + idx) * DF + tid];
                qstar[64 + tid] = r / denom;
                qstar[tid] = q[tid];
            }
        } else {
            if (tid < DF) { qstar[tid] = q[tid]; qstar[64 + tid] = 0.0f; }
        }
        __syncthreads();
    }

    if (tid < NOUT) {
        float acc = b_out[tid];
#pragma unroll
        for (int d = 0; d < DF; d++) acc += q[d] * W_out[d * NOUT + tid];
        out[b * NOUT + tid] = acc;
    }
}

// ---------------- launcher ----------------
extern "C" void kernel_launch(void* const* d_in, const int* in_sizes, int n_in,
                              void* d_out, int out_size) {
    const float* node_features = (const float*)d_in[0];
    const float* edge_features = (const float*)d_in[1];
    const int*   Esrc          = (const int*)d_in[2];
    const int*   Etgt          = (const int*)d_in[3];
    const int*   batch         = (const int*)d_in[4];
    const float* W_in  = (const float*)d_in[5];
    const float* b_in  = (const float*)d_in[6];
    const float* W_ee1 = (const float*)d_in[7];
    const float* b_ee1 = (const float*)d_in[8];
    const float* W_ee2 = (const float*)d_in[9];
    const float* b_ee2 = (const float*)d_in[10];
    const float* W_ih  = (const float*)d_in[11];
    const float* W_hh  = (const float*)d_in[12];
    const float* b_ih  = (const float*)d_in[13];
    const float* b_hh  = (const float*)d_in[14];
    const float* Wl_ih = (const float*)d_in[15];
    const float* Wl_hh = (const float*)d_in[16];
    const float* bl_ih = (const float*)d_in[17];
    const float* bl_hh = (const float*)d_in[18];
    const float* W_out = (const float*)d_in[19];
    const float* b_out = (const float*)d_in[20];
    float* out = (float*)d_out;

    __nv_bfloat16 *p_hbh, *p_hbl, *p_W2bh, *p_W2bl, *p_Whbh, *p_Whbl;
    float *p_Tc, *p_ghb, *p_agg, *p_gi;
    int *p_scnt, *p_tcnt, *p_scur, *p_tcur, *p_ssorted, *p_tsorted, *p_soff, *p_toff;
    cudaGetSymbolAddress((void**)&p_hbh,     g_hbh);
    cudaGetSymbolAddress((void**)&p_hbl,     g_hbl);
    cudaGetSymbolAddress((void**)&p_W2bh,    g_W2bh);
    cudaGetSymbolAddress((void**)&p_W2bl,    g_W2bl);
    cudaGetSymbolAddress((void**)&p_Whbh,    g_Whbh);
    cudaGetSymbolAddress((void**)&p_Whbl,    g_Whbl);
    cudaGetSymbolAddress((void**)&p_Tc,      g_Tc);
    cudaGetSymbolAddress((void**)&p_ghb,     g_ghb);
    cudaGetSymbolAddress((void**)&p_agg,     g_agg);
    cudaGetSymbolAddress((void**)&p_gi,      g_gi);
    cudaGetSymbolAddress((void**)&p_scnt,    g_scnt);
    cudaGetSymbolAddress((void**)&p_tcnt,    g_tcnt);
    cudaGetSymbolAddress((void**)&p_scur,    g_scur);
    cudaGetSymbolAddress((void**)&p_tcur,    g_tcur);
    cudaGetSymbolAddress((void**)&p_ssorted, g_ssorted);
    cudaGetSymbolAddress((void**)&p_tsorted, g_tsorted);
    cudaGetSymbolAddress((void**)&p_soff,    g_soff);
    cudaGetSymbolAddress((void**)&p_toff,    g_toff);

    // --- prep (slots 1..3) ---
    prep_kernel<<<(DF * 4096 + DF * 256 + 255) / 256, 256>>>(W_ee2, b_ee2, W_hh);
    edge_enc_kernel<<<NE / 4, 256>>>(edge_features, W_ee1, b_ee1);
    input_proj_kernel<<<NN / 4, 256>>>(node_features, W_in, b_in);

    // --- slot 4: step-0 chunk-0 GEMM, hoisted ---
    {
        dim3 g(TCC / 64, NN / 64);
        gemm_bf16x3_kernel<<<g, 128>>>(p_hbh, p_hbl, p_W2bh, p_W2bl, p_Tc, 4096, TCC);
    }

    segoff_kernel<<<1, 128>>>(batch);
    // src sort
    cudaMemsetAsync(p_scnt, 0, NN * sizeof(int));
    count_kernel<<<NE / 256, 256>>>(Esrc, p_scnt);
    scan_kernel<<<1, 1024>>>(p_scnt, p_scur, p_soff);
    scatter_kernel<<<NE / 256, 256>>>(Esrc, p_scur, p_ssorted);
    // tgt sort
    cudaMemsetAsync(p_tcnt, 0, NN * sizeof(int));
    count_kernel<<<NE / 256, 256>>>(Etgt, p_tcnt);
    scan_kernel<<<1, 1024>>>(p_tcnt, p_tcur, p_toff);
    scatter_kernel<<<NE / 256, 256>>>(Etgt, p_tcur, p_tsorted);

    // --- message passing ---
    for (int t = 0; t < TMP; t++) {
        {   // ghb = h @ [W_hh | B2]
            dim3 g(256 / 64, NN / 64);
            gemm_bf16x3_kernel<<<g, 128>>>(p_hbh, p_hbl, p_Whbh, p_Whbl, p_ghb, 256, 256);
        }
        for (int kc = 0; kc < NCHUNK; kc++) {
            if (!(t == 0 && kc == 0)) {
                dim3 g(TCC / 64, NN / 64);
                gemm_bf16x3_kernel<<<g, 128>>>(p_hbh, p_hbl,
                                               p_W2bh + kc * TCC, p_W2bl + kc * TCC,
                                               p_Tc, 4096, TCC);
            }
            node_msg_chunk_kernel<<<NN / 4, 256>>>(kc, kc == NCHUNK - 1);
        }
        reduce_agg_kernel<<<NN / 4, 256>>>();
        {   // gi = agg @ W_ih
            dim3 g(192 / 64, NN / 64);
            gemm_tf32x3_kernel<<<g, 128>>>(p_agg, W_ih, p_gi, 192, 192);
        }
        gru_kernel<<<(NN * DF + 255) / 256, 256>>>(b_ih, b_hh);
    }

    // --- set2set + output head ---
    set2set_kernel<<<NB, 256>>>(Wl_ih, Wl_hh, bl_ih, bl_hh, W_out, b_out, out);
}

// round 12
// speedup vs baseline: 1.1760x; 1.1760x over previous
#include <cuda_runtime.h>
#include <cuda_bf16.h>
#include <math.h>
#include <mma.h>
#include <stdint.h>

using namespace nvcuda;

// ---------------- problem constants ----------------
#define NN   8192
#define NE   32768
#define NB   64
#define DF   64
#define NFI  32
#define EFI  16
#define NOUT 12
#define TMP  3
#define TS2S 12

#define KCH    16                 // k values per chunk
#define NCHUNK (DF / KCH)         // 4 chunks
#define TCC    (KCH * DF)         // 1024 columns per Tc chunk

// ---------------- device scratch ----------------
__device__ __align__(16) float g_ed[NE * DF];                   // 8 MB
__device__ __align__(16) __nv_bfloat16 g_W2bh[DF * 4096];       // W2 perm bf16-hi
__device__ __align__(16) __nv_bfloat16 g_W2bl[DF * 4096];       // W2 perm bf16-lo
__device__ __align__(16) __nv_bfloat16 g_Whbh[DF * 256];        // [W_hh|B2] bf16-hi
__device__ __align__(16) __nv_bfloat16 g_Whbl[DF * 256];        // [W_hh|B2] bf16-lo
__device__ __align__(16) float g_Tc[(size_t)NN * TCC];          // 33.5 MB (L2-resident)
__device__ __align__(16) float g_ghb[NN * 256];                 // 8 MB
__device__ __align__(16) float g_h[NN * DF];                    // 2 MB
__device__ __align__(16) __nv_bfloat16 g_hbh[NN * DF];          // 1 MB
__device__ __align__(16) __nv_bfloat16 g_hbl[NN * DF];          // 1 MB
__device__ __align__(16) float g_agg[NN * DF];                  // 2 MB
__device__ __align__(16) float g_gi[NN * 3 * DF];               // 6 MB
__device__ int g_segoff[NB + 1];
__device__ int g_scnt[NN];
__device__ int g_scur[NN];
__device__ int g_sorted[NE];

__device__ __forceinline__ float sigmoidf_(float x) { return 1.0f / (1.0f + expf(-x)); }

__device__ __forceinline__ void split_bf16(float x, __nv_bfloat16& hi, __nv_bfloat16& lo) {
    hi = __float2bfloat16(x);
    lo = __float2bfloat16(x - __bfloat162float(hi));
}

// ---------------- prep: pack + bf16-split W2 (k-major) and Whb = [W_hh | B2] ----------------
__global__ void prep_kernel(const float* __restrict__ W_ee2,
                            const float* __restrict__ b_ee2,
                            const float* __restrict__ W_hh) {
    int idx = blockIdx.x * blockDim.x + threadIdx.x;
    if (idx < DF * 4096) {
        int j = idx >> 12;
        int c = idx & 4095;
        int k = c >> 6, i = c & 63;
        float v = W_ee2[k * 4096 + i * 64 + j];
        __nv_bfloat16 hi, lo; split_bf16(v, hi, lo);
        g_W2bh[idx] = hi; g_W2bl[idx] = lo;
    } else if (idx < DF * 4096 + DF * 256) {
        int idx2 = idx - DF * 4096;
        int j = idx2 >> 8;
        int c = idx2 & 255;
        float v = (c < 192) ? W_hh[j * 192 + c] : b_ee2[(c - 192) * 64 + j];
        __nv_bfloat16 hi, lo; split_bf16(v, hi, lo);
        g_Whbh[idx2] = hi; g_Whbl[idx2] = lo;
    }
}

// ---------------- edge encoder layer 1 ----------------
__global__ void edge_enc_kernel(const float* __restrict__ ef,
                                const float* __restrict__ W1,
                                const float* __restrict__ b1) {
    __shared__ float w1s[EFI * DF];
    __shared__ float b1s[DF];
    __shared__ float efs[4][EFI];
    int tid = threadIdx.x;
    int e0 = blockIdx.x * 4;
    for (int it = tid; it < EFI * DF; it += 256) w1s[it] = W1[it];
    if (tid < DF) b1s[tid] = b1[tid];
    if (tid < 4 * EFI) efs[tid / EFI][tid % EFI] = ef[(e0 + tid / EFI) * EFI + (tid % EFI)];
    __syncthreads();
    int le = tid / DF;
    int d  = tid % DF;
    float acc = b1s[d];
#pragma unroll
    for (int f = 0; f < EFI; f++) acc += efs[le][f] * w1s[f * DF + d];
    g_ed[(e0 + le) * DF + d] = fmaxf(acc, 0.0f);
}

// ---------------- input projection (+ bf16 hi/lo split) ----------------
__global__ void input_proj_kernel(const float* __restrict__ nf,
                                  const float* __restrict__ W,
                                  const float* __restrict__ b) {
    __shared__ float ws[NFI * DF];
    __shared__ float bs[DF];
    __shared__ float nfs[4][NFI];
    int tid = threadIdx.x;
    int n0 = blockIdx.x * 4;
    for (int it = tid; it < NFI * DF; it += 256) ws[it] = W[it];
    if (tid < DF) bs[tid] = b[tid];
    if (tid < 4 * NFI) nfs[tid / NFI][tid % NFI] = nf[(n0 + tid / NFI) * NFI + (tid % NFI)];
    __syncthreads();
    int ln = tid / DF;
    int d  = tid % DF;
    float acc = bs[d];
#pragma unroll
    for (int f = 0; f < NFI; f++) acc += nfs[ln][f] * ws[f * DF + d];
    int o = (n0 + ln) * DF + d;
    g_h[o] = acc;
    __nv_bfloat16 hi, lo; split_bf16(acc, hi, lo);
    g_hbh[o] = hi; g_hbl[o] = lo;
}

// ---------------- segment offsets ----------------
__global__ void segoff_kernel(const int* __restrict__ batch) {
    int g = threadIdx.x;
    if (g > NB) return;
    if (g == NB) { g_segoff[NB] = NN; return; }
    int lo = 0, hi = NN;
    while (lo < hi) { int mid = (lo + hi) >> 1; if (batch[mid] < g) lo = mid + 1; else hi = mid; }
    g_segoff[g] = lo;
}

// ---------------- edge sort by src ----------------
__global__ void count_kernel(const int* __restrict__ Esrc) {
    int e = blockIdx.x * blockDim.x + threadIdx.x;
    if (e < NE) atomicAdd(&g_scnt[Esrc[e]], 1);
}

__global__ void scan_kernel() {
    __shared__ int part[1024];
    int tid = threadIdx.x;
    int loc[8]; int s = 0;
#pragma unroll
    for (int i = 0; i < 8; i++) { loc[i] = s; s += g_scnt[tid * 8 + i]; }
    part[tid] = s;
    __syncthreads();
    for (int off = 1; off < 1024; off <<= 1) {
        int t = (tid >= off) ? part[tid - off] : 0;
        __syncthreads();
        part[tid] += t;
        __syncthreads();
    }
    int excl = tid ? part[tid - 1] : 0;
#pragma unroll
    for (int i = 0; i < 8; i++) g_scur[tid * 8 + i] = excl + loc[i];
}

__global__ void scatter_kernel(const int* __restrict__ Esrc) {
    int e = blockIdx.x * blockDim.x + threadIdx.x;
    if (e >= NE) return;
    int p = atomicAdd(&g_scur[Esrc[e]], 1);
    g_sorted[p] = e;
}

// ---------------- WIDE bf16x3 GEMM: 64x128 block tile, 128 threads ----------------
// C[8192, Nc] = (Ah+Al)[8192,64] @ (Bh+Bl)[64,Nc]. 4 warps, each 32x64 (2x4 frags).
// 12 fragment loads per 24 MMAs per warp-ks (vs 8/12 in the 64x64 version).
// Dynamic smem layout (bf16 elems): Ah[64][72] | Al[64][72] | Bh[64][136] | Bl[64][136]
#define WG_SMEM_ELEMS (2 * 64 * 72 + 2 * 64 * 136)
#define WG_SMEM_BYTES (WG_SMEM_ELEMS * 2)

__global__ void __launch_bounds__(128)
gemm_bf16x3_wide_kernel(const __nv_bfloat16* __restrict__ Abh,
                        const __nv_bfloat16* __restrict__ Abl,
                        const __nv_bfloat16* __restrict__ Bbh,
                        const __nv_bfloat16* __restrict__ Bbl,
                        float* __restrict__ C, int ldb, int ldc) {
    extern __shared__ __nv_bfloat16 smem[];
    __nv_bfloat16 (*Ah)[72]  = (__nv_bfloat16(*)[72])(smem);
    __nv_bfloat16 (*Al)[72]  = (__nv_bfloat16(*)[72])(smem + 64 * 72);
    __nv_bfloat16 (*Bh)[136] = (__nv_bfloat16(*)[136])(smem + 2 * 64 * 72);
    __nv_bfloat16 (*Bl)[136] = (__nv_bfloat16(*)[136])(smem + 2 * 64 * 72 + 64 * 136);
    int tid = threadIdx.x;
    int m0 = blockIdx.y * 64;
    int n0 = blockIdx.x * 128;
    // A: 64x64 = 512 uint4
#pragma unroll
    for (int it = 0; it < 4; it++) {
        int idx = tid + it * 128;
        int row = idx >> 3;
        int c8  = (idx & 7) << 3;
        *(uint4*)&Ah[row][c8] = *(const uint4*)&Abh[(size_t)(m0 + row) * 64 + c8];
        *(uint4*)&Al[row][c8] = *(const uint4*)&Abl[(size_t)(m0 + row) * 64 + c8];
    }
    // B: 64x128 = 1024 uint4
#pragma unroll
    for (int it = 0; it < 8; it++) {
        int idx = tid + it * 128;
        int row = idx >> 4;
        int c8  = (idx & 15) << 3;
        *(uint4*)&Bh[row][c8] = *(const uint4*)&Bbh[(size_t)row * ldb + n0 + c8];
        *(uint4*)&Bl[row][c8] = *(const uint4*)&Bbl[(size_t)row * ldb + n0 + c8];
    }
    __syncthreads();
    int warp = tid >> 5;
    int wm = warp >> 1;            // 0..1 -> rows wm*32
    int wn = warp & 1;             // 0..1 -> cols wn*64
    wmma::fragment<wmma::accumulator, 16, 16, 16, float> acc[2][4];
#pragma unroll
    for (int i = 0; i < 2; i++)
#pragma unroll
        for (int j = 0; j < 4; j++) wmma::fill_fragment(acc[i][j], 0.0f);
#pragma unroll
    for (int ks = 0; ks < 4; ks++) {
        wmma::fragment<wmma::matrix_a, 16, 16, 16, __nv_bfloat16, wmma::row_major> ah[2], al[2];
#pragma unroll
        for (int i = 0; i < 2; i++) {
            wmma::load_matrix_sync(ah[i], &Ah[wm * 32 + i * 16][ks * 16], 72);
            wmma::load_matrix_sync(al[i], &Al[wm * 32 + i * 16][ks * 16], 72);
        }
#pragma unroll
        for (int j = 0; j < 4; j++) {
            wmma::fragment<wmma::matrix_b, 16, 16, 16, __nv_bfloat16, wmma::row_major> bh, bl;
            wmma::load_matrix_sync(bh, &Bh[ks * 16][wn * 64 + j * 16], 136);
            wmma::load_matrix_sync(bl, &Bl[ks * 16][wn * 64 + j * 16], 136);
#pragma unroll
            for (int i = 0; i < 2; i++) {
                wmma::mma_sync(acc[i][j], al[i], bh, acc[i][j]);
                wmma::mma_sync(acc[i][j], ah[i], bl, acc[i][j]);
                wmma::mma_sync(acc[i][j], ah[i], bh, acc[i][j]);
            }
        }
    }
#pragma unroll
    for (int i = 0; i < 2; i++)
#pragma unroll
        for (int j = 0; j < 4; j++)
            wmma::store_matrix_sync(
                &C[(size_t)(m0 + wm * 32 + i * 16) * ldc + n0 + wn * 64 + j * 16],
                acc[i][j], ldc, wmma::mem_row_major);
}

// ---------------- legacy tf32x3 GEMM (gi = agg @ W_ih only) ----------------
__global__ void gemm_tf32x3_kernel(const float* __restrict__ A,
                                   const float* __restrict__ Bm,
                                   float* __restrict__ C,
                                   int ldb, int ldc) {
    __shared__ float As[64][68];
    __shared__ float Bs[64][68];
    int tid = threadIdx.x;
    int m0 = blockIdx.y * 64;
    int n0 = blockIdx.x * 64;
#pragma unroll
    for (int it = 0; it < 8; it++) {
        int idx = tid + it * 128;
        int row = idx >> 4;
        int c4  = (idx & 15) << 2;
        float4 va = *(const float4*)&A[(size_t)(m0 + row) * 64 + c4];
        As[row][c4 + 0] = va.x; As[row][c4 + 1] = va.y;
        As[row][c4 + 2] = va.z; As[row][c4 + 3] = va.w;
        float4 vb = *(const float4*)&Bm[(size_t)row * ldb + n0 + c4];
        Bs[row][c4 + 0] = vb.x; Bs[row][c4 + 1] = vb.y;
        Bs[row][c4 + 2] = vb.z; Bs[row][c4 + 3] = vb.w;
    }
    __syncthreads();
    int warp = tid >> 5;
    int wm = warp >> 1;
    int wn = warp & 1;
    wmma::fragment<wmma::accumulator, 16, 16, 8, float> acc[2][2];
#pragma unroll
    for (int i = 0; i < 2; i++)
#pragma unroll
        for (int j = 0; j < 2; j++) wmma::fill_fragment(acc[i][j], 0.0f);
#pragma unroll
    for (int ks = 0; ks < 8; ks++) {
        wmma::fragment<wmma::matrix_a, 16, 16, 8, wmma::precision::tf32, wmma::row_major> ah[2], al[2];
        wmma::fragment<wmma::matrix_b, 16, 16, 8, wmma::precision::tf32, wmma::row_major> bh[2], bl[2];
#pragma unroll
        for (int i = 0; i < 2; i++) {
            wmma::load_matrix_sync(ah[i], &As[wm * 32 + i * 16][ks * 8], 68);
#pragma unroll
            for (int t = 0; t < ah[i].num_elements; t++) {
                float x  = ah[i].x[t];
                float hi = wmma::__float_to_tf32(x);
                al[i].x[t] = wmma::__float_to_tf32(x - hi);
                ah[i].x[t] = hi;
            }
        }
#pragma unroll
        for (int j = 0; j < 2; j++) {
            wmma::load_matrix_sync(bh[j], &Bs[ks * 8][wn * 32 + j * 16], 68);
#pragma unroll
            for (int t = 0; t < bh[j].num_elements; t++) {
                float x  = bh[j].x[t];
                float hi = wmma::__float_to_tf32(x);
                bl[j].x[t] = wmma::__float_to_tf32(x - hi);
                bh[j].x[t] = hi;
            }
        }
#pragma unroll
        for (int i = 0; i < 2; i++)
#pragma unroll
            for (int j = 0; j < 2; j++) {
                wmma::mma_sync(acc[i][j], al[i], bh[j], acc[i][j]);
                wmma::mma_sync(acc[i][j], ah[i], bl[j], acc[i][j]);
                wmma::mma_sync(acc[i][j], ah[i], bh[j], acc[i][j]);
            }
    }
#pragma unroll
    for (int i = 0; i < 2; i++)
#pragma unroll
        for (int j = 0; j < 2; j++)
            wmma::store_matrix_sync(
                &C[(size_t)(m0 + wm * 32 + i * 16) * ldc + n0 + wn * 32 + j * 16],
                acc[i][j], ldc, wmma::mem_row_major);
}

// ---------------- edge message chunk + scatter (R9-proven, KCH=16, atomics) ----------------
__global__ void edge_msg_chunk_kernel(const int* __restrict__ Esrc,
                                      const int* __restrict__ Etgt,
                                      int kc, int last) {
    __shared__ float eds[4][KCH];
    int tid = threadIdx.x;
    int le  = tid >> 6;
    int i   = tid & 63;
    int e   = g_sorted[blockIdx.x * 4 + le];
    if (i < KCH) eds[le][i] = g_ed[e * DF + kc * KCH + i];
    int src = Esrc[e];
    int tgt = Etgt[e];
    __syncthreads();
    const float* Trow = &g_Tc[(size_t)src * TCC];
    float acc = 0.0f;
#pragma unroll
    for (int kk = 0; kk < KCH; kk++) acc += eds[le][kk] * Trow[kk * DF + i];
    if (last) acc += g_ghb[src * 256 + 192 + i];
    atomicAdd(&g_agg[tgt * DF + i], acc);
}

// ---------------- GRU update; writes h + bf16 hi/lo ----------------
__global__ void gru_kernel(const float* __restrict__ b_ih,
                           const float* __restrict__ b_hh) {
    int idx = blockIdx.x * blockDim.x + threadIdx.x;
    if (idx >= NN * DF) return;
    int n = idx / DF;
    int d = idx % DF;
    const float* ghrow = &g_ghb[n * 256];
    float gh_r = ghrow[d]       + b_hh[d];
    float gh_z = ghrow[64 + d]  + b_hh[64 + d];
    float gh_n = ghrow[128 + d] + b_hh[128 + d];
    const float* gi = &g_gi[n * 192];
    float gi_r = gi[d]       + b_ih[d];
    float gi_z = gi[64 + d]  + b_ih[64 + d];
    float gi_n = gi[128 + d] + b_ih[128 + d];
    float r = sigmoidf_(gi_r + gh_r);
    float z = sigmoidf_(gi_z + gh_z);
    float nn = tanhf(gi_n + r * gh_n);
    float h = g_h[idx];
    float v = (1.0f - z) * nn + z * h;
    g_h[idx] = v;
    __nv_bfloat16 hi, lo; split_bf16(v, hi, lo);
    g_hbh[idx] = hi; g_hbl[idx] = lo;
}

// ---------------- fused Set2Set + output head ----------------
#define MAXSEG 2048
__global__ void set2set_kernel(const float* __restrict__ Wl_ih,
                               const float* __restrict__ Wl_hh,
                               const float* __restrict__ bl_ih,
                               const float* __restrict__ bl_hh,
                               const float* __restrict__ W_out,
                               const float* __restrict__ b_out,
                               float* __restrict__ out) {
    __shared__ float q[DF], hs[DF], cs[DF], qstar[2 * DF], gates[4 * DF];
    __shared__ float evals[MAXSEG];
    __shared__ float redmax[8], redsum[8];
    int b   = blockIdx.x;
    int tid = threadIdx.x;
    int lane = tid & 31, w = tid >> 5;
    int start = g_segoff[b], end = g_segoff[b + 1];
    int cnt = end - start;
    if (tid < DF) { hs[tid] = 0.0f; cs[tid] = 0.0f; }
    if (tid < 2 * DF) qstar[tid] = 0.0f;
    __syncthreads();

    for (int s = 0; s < TS2S; s++) {
        float acc = bl_ih[tid] + bl_hh[tid];
#pragma unroll 4
        for (int j = 0; j < 2 * DF; j++) acc += qstar[j] * Wl_ih[j * 256 + tid];
#pragma unroll 4
        for (int j = 0; j < DF; j++)     acc += hs[j] * Wl_hh[j * 256 + tid];
        gates[tid] = acc;
        __syncthreads();
        if (tid < DF) {
            float i_ = gates[tid], f_ = gates[64 + tid], g_ = gates[128 + tid], o_ = gates[192 + tid];
            float cc = sigmoidf_(f_) * cs[tid] + sigmoidf_(i_) * tanhf(g_);
            cs[tid] = cc;
            float hh = sigmoidf_(o_) * tanhf(cc);
            hs[tid] = hh;
            q[tid] = hh;
        }
        __syncthreads();
        if (s == TS2S - 1) break;

        if (cnt > 0) {
            for (int idx = w; idx < cnt; idx += 8) {
                const float* xr = &g_h[(size_t)(start + idx) * DF];
                float p = xr[lane] * q[lane] + xr[lane + 32] * q[lane + 32];
#pragma unroll
                for (int o = 16; o; o >>= 1) p += __shfl_xor_sync(0xffffffffu, p, o);
                if (lane == 0) evals[idx] = p;
            }
            __syncthreads();
            float m = -INFINITY;
            for (int idx = tid; idx < cnt; idx += 256) m = fmaxf(m, evals[idx]);
#pragma unroll
            for (int o = 16; o; o >>= 1) m = fmaxf(m, __shfl_xor_sync(0xffffffffu, m, o));
            if (lane == 0) redmax[w] = m;
            __syncthreads();
            float emax = redmax[0];
#pragma unroll
            for (int k = 1; k < 8; k++) emax = fmaxf(emax, redmax[k]);
            float dsum = 0.0f;
            for (int idx = tid; idx < cnt; idx += 256) {
                float ex = expf(evals[idx] - emax);
                evals[idx] = ex;
                dsum += ex;
            }
#pragma unroll
            for (int o = 16; o; o >>= 1) dsum += __shfl_xor_sync(0xffffffffu, dsum, o);
            if (lane == 0) redsum[w] = dsum;
            __syncthreads();
            float denom = 0.0f;
#pragma unroll
            for (int k = 0; k < 8; k++) denom += redsum[k];
            if (tid < DF) {
                float r = 0.0f;
                for (int idx = 0; idx < cnt; idx++)
                    r += evals[idx] * g_h[(size_t)(start + idx) * DF + tid];
                qstar[64 + tid] = r / denom;
                qstar[tid] = q[tid];
            }
        } else {
            if (tid < DF) { qstar[tid] = q[tid]; qstar[64 + tid] = 0.0f; }
        }
        __syncthreads();
    }

    if (tid < NOUT) {
        float acc = b_out[tid];
#pragma unroll
        for (int d = 0; d < DF; d++) acc += q[d] * W_out[d * NOUT + tid];
        out[b * NOUT + tid] = acc;
    }
}

// ---------------- launcher ----------------
extern "C" void kernel_launch(void* const* d_in, const int* in_sizes, int n_in,
                              void* d_out, int out_size) {
    const float* node_features = (const float*)d_in[0];
    const float* edge_features = (const float*)d_in[1];
    const int*   Esrc          = (const int*)d_in[2];
    const int*   Etgt          = (const int*)d_in[3];
    const int*   batch         = (const int*)d_in[4];
    const float* W_in  = (const float*)d_in[5];
    const float* b_in  = (const float*)d_in[6];
    const float* W_ee1 = (const float*)d_in[7];
    const float* b_ee1 = (const float*)d_in[8];
    const float* W_ee2 = (const float*)d_in[9];
    const float* b_ee2 = (const float*)d_in[10];
    const float* W_ih  = (const float*)d_in[11];
    const float* W_hh  = (const float*)d_in[12];
    const float* b_ih  = (const float*)d_in[13];
    const float* b_hh  = (const float*)d_in[14];
    const float* Wl_ih = (const float*)d_in[15];
    const float* Wl_hh = (const float*)d_in[16];
    const float* bl_ih = (const float*)d_in[17];
    const float* bl_hh = (const float*)d_in[18];
    const float* W_out = (const float*)d_in[19];
    const float* b_out = (const float*)d_in[20];
    float* out = (float*)d_out;

    __nv_bfloat16 *p_hbh, *p_hbl, *p_W2bh, *p_W2bl, *p_Whbh, *p_Whbl;
    float *p_Tc, *p_ghb, *p_agg, *p_gi;
    int *p_scnt;
    cudaGetSymbolAddress((void**)&p_hbh,  g_hbh);
    cudaGetSymbolAddress((void**)&p_hbl,  g_hbl);
    cudaGetSymbolAddress((void**)&p_W2bh, g_W2bh);
    cudaGetSymbolAddress((void**)&p_W2bl, g_W2bl);
    cudaGetSymbolAddress((void**)&p_Whbh, g_Whbh);
    cudaGetSymbolAddress((void**)&p_Whbl, g_Whbl);
    cudaGetSymbolAddress((void**)&p_Tc,   g_Tc);
    cudaGetSymbolAddress((void**)&p_ghb,  g_ghb);
    cudaGetSymbolAddress((void**)&p_agg,  g_agg);
    cudaGetSymbolAddress((void**)&p_gi,   g_gi);
    cudaGetSymbolAddress((void**)&p_scnt, g_scnt);

    cudaFuncSetAttribute(gemm_bf16x3_wide_kernel,
                         cudaFuncAttributeMaxDynamicSharedMemorySize, WG_SMEM_BYTES);

    // --- prep (slots 1..3) ---
    prep_kernel<<<(DF * 4096 + DF * 256 + 255) / 256, 256>>>(W_ee2, b_ee2, W_hh);
    edge_enc_kernel<<<NE / 4, 256>>>(edge_features, W_ee1, b_ee1);
    input_proj_kernel<<<NN / 4, 256>>>(node_features, W_in, b_in);

    // --- slot 4: step-0 chunk-0 GEMM, hoisted (skipped inside loop at t=0,kc=0) ---
    {
        dim3 g(TCC / 128, NN / 64);
        gemm_bf16x3_wide_kernel<<<g, 128, WG_SMEM_BYTES>>>(p_hbh, p_hbl, p_W2bh, p_W2bl,
                                                           p_Tc, 4096, TCC);
    }

    segoff_kernel<<<1, 128>>>(batch);
    cudaMemsetAsync(p_scnt, 0, NN * sizeof(int));
    count_kernel<<<NE / 256, 256>>>(Esrc);
    scan_kernel<<<1, 1024>>>();
    scatter_kernel<<<NE / 256, 256>>>(Esrc);

    // --- message passing ---
    for (int t = 0; t < TMP; t++) {
        cudaMemsetAsync(p_agg, 0, NN * DF * sizeof(float));
        {   // ghb = h @ [W_hh | B2]
            dim3 g(256 / 128, NN / 64);
            gemm_bf16x3_wide_kernel<<<g, 128, WG_SMEM_BYTES>>>(p_hbh, p_hbl, p_Whbh, p_Whbl,
                                                               p_ghb, 256, 256);
        }
        for (int kc = 0; kc < NCHUNK; kc++) {
            if (!(t == 0 && kc == 0)) {
                dim3 g(TCC / 128, NN / 64);
                gemm_bf16x3_wide_kernel<<<g, 128, WG_SMEM_BYTES>>>(p_hbh, p_hbl,
                                                                   p_W2bh + kc * TCC,
                                                                   p_W2bl + kc * TCC,
                                                                   p_Tc, 4096, TCC);
            }
            edge_msg_chunk_kernel<<<NE / 4, 256>>>(Esrc, Etgt, kc, kc == NCHUNK - 1);
        }
        {   // gi = agg @ W_ih
            dim3 g(192 / 64, NN / 64);
            gemm_tf32x3_kernel<<<g, 128>>>(p_agg, W_ih, p_gi, 192, 192);
        }
        gru_kernel<<<(NN * DF + 255) / 256, 256>>>(b_ih, b_hh);
    }

    // --- set2set + output head ---
    set2set_kernel<<<NB, 256>>>(Wl_ih, Wl_hh, bl_ih, bl_hh, W_out, b_out, out);
}